// round 10
// baseline (speedup 1.0000x reference)
#include <cuda_runtime.h>
#include <cuda_fp16.h>

#define N_NODES  100000
#define IN_DIM   256
#define OUT_DIM  128
#define FEAT_NNZ 1000000
#define ADJ_NNZ  1600000

#define TILE      1024
#define NBLK      ((N_NODES + TILE - 1) / TILE)   // 98
#define SGRID     (2 * NBLK)                      // 196 blocks, all co-resident
#define GSTRIDE   (SGRID * TILE)                  // 200704 threads

#define T         256
#define FBH       ((FEAT_NNZ / 2 + T - 1) / T)    // hist blocks (feat, 2/thread)
#define ABH       ((ADJ_NNZ  / 2 + T - 1) / T)    // hist/scatter blocks (adj)
#define ROWS_GRID ((N_NODES + 7) / 8)             // 12500 spmm row blocks

// ---------------------------------------------------------------------------
// Scratch (__device__ globals; zero-initialized at module load; referenced
// ONLY from device code). cnt arrays and barrier counters are restored to 0
// by the kernels themselves, so every graph replay sees identical state.
// ---------------------------------------------------------------------------
__device__ uint2  g_xw2[(size_t)N_NODES * 32];            // XW fp16, 25.6 MB

__device__ int    g_feat_cnt [N_NODES];
__device__ int    g_feat_ptr [N_NODES + 1];
__device__ int    g_feat_rank[FEAT_NNZ];                  // within-row rank
__device__ float2 g_feat_csr [FEAT_NNZ];                  // {val, col bits}
__device__ int    g_feat_bsum[NBLK];

__device__ int    g_adj_cnt [N_NODES];
__device__ int    g_adj_ptr [N_NODES + 1];
__device__ int    g_adj_rank[ADJ_NNZ];
__device__ float2 g_adj_csr [ADJ_NNZ];
__device__ int    g_adj_bsum[NBLK];

// grid-barrier state for the fused scan+scatter kernel (self-resetting)
__device__ int    g_barA, g_goA, g_barB, g_goB, g_barC;

// ---------------------------------------------------------------------------
// 1. Fused row histogram, 2 entries/thread, capturing each entry's
//    within-row rank (the atomic's return). Scatter then needs NO atomics.
// ---------------------------------------------------------------------------
__global__ void hist_both_kernel(const int2* __restrict__ feat_rows2,
                                 const int2* __restrict__ adj_rows2) {
    if (blockIdx.x < FBH) {
        int i = blockIdx.x * T + threadIdx.x;      // pair index
        int base = i * 2;
        if (base < FEAT_NNZ) {                     // FEAT_NNZ even -> both valid
            int2 r = __ldg(&feat_rows2[i]);
            g_feat_rank[base]     = atomicAdd(&g_feat_cnt[r.x], 1);
            g_feat_rank[base + 1] = atomicAdd(&g_feat_cnt[r.y], 1);
        }
    } else {
        int i = (blockIdx.x - FBH) * T + threadIdx.x;
        int base = i * 2;
        if (base < ADJ_NNZ) {                      // ADJ_NNZ even -> both valid
            int2 r = __ldg(&adj_rows2[i]);
            g_adj_rank[base]     = atomicAdd(&g_adj_cnt[r.x], 1);
            g_adj_rank[base + 1] = atomicAdd(&g_adj_cnt[r.y], 1);
        }
    }
}

// ---------------------------------------------------------------------------
// Device-wide barrier for the SGRID-block kernel (all blocks co-resident:
// 196 blocks of 1024 threads <= 148 SMs * 2 blocks). Spin on an L2 flag.
// ---------------------------------------------------------------------------
__device__ __forceinline__ void grid_barrier(int* bar, int* go) {
    __syncthreads();
    if (threadIdx.x == 0) {
        __threadfence();
        int old = atomicAdd(bar, 1);
        if (old == SGRID - 1) atomicExch(go, 1);
        while (atomicAdd(go, 0) == 0) { }
        __threadfence();
    }
    __syncthreads();
}

// ---------------------------------------------------------------------------
// 2. FUSED scan + feat scatter (one kernel, two internal grid barriers):
//    phase A: per-tile sums of cnt          (as scan_p1)
//    phase B: self-offsetting tile scan -> ptr, zero cnt   (as scan_p3)
//    phase C: feat COO -> CSR scatter, grid-stride, 2-way batched
//    epilogue: last block resets all barrier state (replay invariant).
// ---------------------------------------------------------------------------
__global__ void __launch_bounds__(TILE, 2)
scan_scatter_feat_kernel(const float* __restrict__ feat_vals,
                         const int*   __restrict__ feat_rows,
                         const int*   __restrict__ feat_cols) {
    int which = (blockIdx.x >= NBLK);
    int blk   = which ? (blockIdx.x - NBLK) : blockIdx.x;
    int* __restrict__ cnt        = which ? g_adj_cnt  : g_feat_cnt;
    int* __restrict__ bsum       = which ? g_adj_bsum : g_feat_bsum;
    int* __restrict__ ptr        = which ? g_adj_ptr  : g_feat_ptr;

    __shared__ int s[TILE];
    __shared__ int red[128];
    int t = threadIdx.x;

    // ---- phase A: tile sum ----
    int idx = blk * TILE + t;
    int v   = (idx < N_NODES) ? cnt[idx] : 0;
    s[t] = v;
    __syncthreads();
    for (int off = TILE >> 1; off > 0; off >>= 1) {
        if (t < off) s[t] += s[t + off];
        __syncthreads();
    }
    if (t == 0) bsum[blk] = s[0];

    grid_barrier(&g_barA, &g_goA);

    // ---- phase B: tile offset + inclusive scan -> ptr; zero cnt ----
    if (t < 128) red[t] = (t < NBLK && t < blk) ? bsum[t] : 0;
    __syncthreads();
    for (int off = 64; off > 0; off >>= 1) {
        if (t < off) red[t] += red[t + off];
        __syncthreads();
    }
    int boff = red[0];
    __syncthreads();

    s[t] = v;
    __syncthreads();
    for (int off = 1; off < TILE; off <<= 1) {
        int u = (t >= off) ? s[t - off] : 0;
        __syncthreads();
        s[t] += u;
        __syncthreads();
    }
    if (idx < N_NODES) {
        ptr[idx] = boff + s[t] - v;
        cnt[idx] = 0;                               // replay invariant
    }
    if (blk == NBLK - 1 && t == TILE - 1) ptr[N_NODES] = boff + s[t];

    grid_barrier(&g_barB, &g_goB);

    // ---- phase C: feat scatter (no atomics), 2-way batched grid-stride ----
    int gtid = blockIdx.x * TILE + t;
    for (int i = gtid; i < FEAT_NNZ; i += 2 * GSTRIDE) {
        int i2 = i + GSTRIDE;
        int  r0 = __ldg(&feat_rows[i]);
        int  k0 = g_feat_rank[i];
        float v0 = __ldg(&feat_vals[i]);
        int  c0 = __ldg(&feat_cols[i]);
        if (i2 < FEAT_NNZ) {
            int  r1 = __ldg(&feat_rows[i2]);
            int  k1 = g_feat_rank[i2];
            float v1 = __ldg(&feat_vals[i2]);
            int  c1 = __ldg(&feat_cols[i2]);
            int p1 = __ldg(&g_feat_ptr[r1]) + k1;
            int p0 = __ldg(&g_feat_ptr[r0]) + k0;
            g_feat_csr[p0] = make_float2(v0, __int_as_float(c0));
            g_feat_csr[p1] = make_float2(v1, __int_as_float(c1));
        } else {
            int p0 = __ldg(&g_feat_ptr[r0]) + k0;
            g_feat_csr[p0] = make_float2(v0, __int_as_float(c0));
        }
    }

    // ---- epilogue: last finishing block resets barrier state ----
    __syncthreads();
    if (t == 0) {
        int old = atomicAdd(&g_barC, 1);
        if (old == SGRID - 1) {        // every block has passed both spins
            atomicExch(&g_barA, 0); atomicExch(&g_goA, 0);
            atomicExch(&g_barB, 0); atomicExch(&g_goB, 0);
            atomicExch(&g_barC, 0);
        }
    }
}

// ---------------------------------------------------------------------------
// 3. FUSED: blocks [0, ABH) scatter the adj COO into CSR (2 entries/thread);
//    blocks [ABH, ...) run SpMM1 over the complete feat CSR. Disjoint data,
//    so the grid overlaps the latency-ish scatter with the gather SpMM1.
// ---------------------------------------------------------------------------
__global__ void adj_scatter_spmm1_kernel(const float2* __restrict__ adj_vals2,
                                         const int2*   __restrict__ adj_rows2,
                                         const int2*   __restrict__ adj_cols2,
                                         const float4* __restrict__ W4) {
    if (blockIdx.x < ABH) {
        // ---- adj scatter, 2 entries/thread ----
        int i = blockIdx.x * T + threadIdx.x;       // pair index
        int base = i * 2;
        if (base >= ADJ_NNZ) return;                // ADJ_NNZ even -> both valid
        int2   r = __ldg(&adj_rows2[i]);
        int2   c = __ldg(&adj_cols2[i]);
        float2 v = __ldg(&adj_vals2[i]);
        int2   k = __ldg(&((const int2*)g_adj_rank)[i]);
        int p0 = __ldg(&g_adj_ptr[r.x]) + k.x;
        int p1 = __ldg(&g_adj_ptr[r.y]) + k.y;
        g_adj_csr[p0] = make_float2(v.x, __int_as_float(c.x));
        g_adj_csr[p1] = make_float2(v.y, __int_as_float(c.y));
        return;
    }

    // ---- SpMM1: XW[row,:] = sum_e val_e * W[col_e,:] ----
    int b    = blockIdx.x - ABH;
    int row  = b * (T >> 5) + (threadIdx.x >> 5);
    if (row >= N_NODES) return;
    int lane = threadIdx.x & 31;

    int s = g_feat_ptr[row];
    int e = g_feat_ptr[row + 1];

    float4 acc = make_float4(0.f, 0.f, 0.f, 0.f);
    int j = s;
    for (; j + 2 <= e; j += 2) {
        float2 vc0 = __ldg(&g_feat_csr[j]);
        float2 vc1 = __ldg(&g_feat_csr[j + 1]);
        int c0 = __float_as_int(vc0.y);
        int c1 = __float_as_int(vc1.y);
        float4 w0 = __ldg(&W4[(size_t)c0 * 32 + lane]);
        float4 w1 = __ldg(&W4[(size_t)c1 * 32 + lane]);
        acc.x += vc0.x * w0.x + vc1.x * w1.x;
        acc.y += vc0.x * w0.y + vc1.x * w1.y;
        acc.z += vc0.x * w0.z + vc1.x * w1.z;
        acc.w += vc0.x * w0.w + vc1.x * w1.w;
    }
    for (; j < e; j++) {
        float2 vc = __ldg(&g_feat_csr[j]);
        int c = __float_as_int(vc.y);
        float4 w = __ldg(&W4[(size_t)c * 32 + lane]);
        acc.x += vc.x * w.x;
        acc.y += vc.x * w.y;
        acc.z += vc.x * w.z;
        acc.w += vc.x * w.w;
    }
    __half2 h0 = __floats2half2_rn(acc.x, acc.y);
    __half2 h1 = __floats2half2_rn(acc.z, acc.w);
    uint2 packed;
    packed.x = *reinterpret_cast<unsigned int*>(&h0);
    packed.y = *reinterpret_cast<unsigned int*>(&h1);
    g_xw2[(size_t)row * 32 + lane] = packed;
}

// ---------------------------------------------------------------------------
// 4. SpMM2 (CSR gather, fp16 XW) + fused bias + ReLU. Unrolled x4 (MLP=4).
// ---------------------------------------------------------------------------
__global__ void spmm2_csr_kernel(float4* __restrict__ out4,
                                 const float4* __restrict__ bias4) {
    int row  = blockIdx.x * (T >> 5) + (threadIdx.x >> 5);
    if (row >= N_NODES) return;
    int lane = threadIdx.x & 31;

    int s = g_adj_ptr[row];
    int e = g_adj_ptr[row + 1];

    float4 acc = make_float4(0.f, 0.f, 0.f, 0.f);
    int j = s;
    for (; j + 4 <= e; j += 4) {
        float2 vc0 = __ldg(&g_adj_csr[j]);
        float2 vc1 = __ldg(&g_adj_csr[j + 1]);
        float2 vc2 = __ldg(&g_adj_csr[j + 2]);
        float2 vc3 = __ldg(&g_adj_csr[j + 3]);
        uint2 r0 = __ldg(&g_xw2[(size_t)__float_as_int(vc0.y) * 32 + lane]);
        uint2 r1 = __ldg(&g_xw2[(size_t)__float_as_int(vc1.y) * 32 + lane]);
        uint2 r2 = __ldg(&g_xw2[(size_t)__float_as_int(vc2.y) * 32 + lane]);
        uint2 r3 = __ldg(&g_xw2[(size_t)__float_as_int(vc3.y) * 32 + lane]);
        float2 a0 = __half22float2(*reinterpret_cast<__half2*>(&r0.x));
        float2 b0 = __half22float2(*reinterpret_cast<__half2*>(&r0.y));
        float2 a1 = __half22float2(*reinterpret_cast<__half2*>(&r1.x));
        float2 b1 = __half22float2(*reinterpret_cast<__half2*>(&r1.y));
        float2 a2 = __half22float2(*reinterpret_cast<__half2*>(&r2.x));
        float2 b2 = __half22float2(*reinterpret_cast<__half2*>(&r2.y));
        float2 a3 = __half22float2(*reinterpret_cast<__half2*>(&r3.x));
        float2 b3 = __half22float2(*reinterpret_cast<__half2*>(&r3.y));
        acc.x += vc0.x * a0.x + vc1.x * a1.x + vc2.x * a2.x + vc3.x * a3.x;
        acc.y += vc0.x * a0.y + vc1.x * a1.y + vc2.x * a2.y + vc3.x * a3.y;
        acc.z += vc0.x * b0.x + vc1.x * b1.x + vc2.x * b2.x + vc3.x * b3.x;
        acc.w += vc0.x * b0.y + vc1.x * b1.y + vc2.x * b2.y + vc3.x * b3.y;
    }
    for (; j < e; j++) {
        float2 vc = __ldg(&g_adj_csr[j]);
        uint2 raw = __ldg(&g_xw2[(size_t)__float_as_int(vc.y) * 32 + lane]);
        float2 f0 = __half22float2(*reinterpret_cast<__half2*>(&raw.x));
        float2 f1 = __half22float2(*reinterpret_cast<__half2*>(&raw.y));
        acc.x += vc.x * f0.x;
        acc.y += vc.x * f0.y;
        acc.z += vc.x * f1.x;
        acc.w += vc.x * f1.y;
    }

    float4 b = __ldg(&bias4[lane]);
    acc.x = fmaxf(acc.x + b.x, 0.f);
    acc.y = fmaxf(acc.y + b.y, 0.f);
    acc.z = fmaxf(acc.z + b.z, 0.f);
    acc.w = fmaxf(acc.w + b.w, 0.f);
    out4[(size_t)row * 32 + lane] = acc;
}

// ---------------------------------------------------------------------------
extern "C" void kernel_launch(void* const* d_in, const int* in_sizes, int n_in,
                              void* d_out, int out_size) {
    const float* feat_vals = (const float*)d_in[0];
    const int*   feat_rows = (const int*)  d_in[1];
    const int*   feat_cols = (const int*)  d_in[2];
    const float* adj_vals  = (const float*)d_in[3];
    const int*   adj_rows  = (const int*)  d_in[4];
    const int*   adj_cols  = (const int*)  d_in[5];
    const float* weights   = (const float*)d_in[6];
    const float* bias_vec  = (const float*)d_in[7];
    float4* out4 = (float4*)d_out;

    hist_both_kernel<<<FBH + ABH, T>>>((const int2*)feat_rows,
                                       (const int2*)adj_rows);

    scan_scatter_feat_kernel<<<SGRID, TILE>>>(feat_vals, feat_rows, feat_cols);

    adj_scatter_spmm1_kernel<<<ABH + ROWS_GRID, T>>>((const float2*)adj_vals,
                                                     (const int2*)adj_rows,
                                                     (const int2*)adj_cols,
                                                     (const float4*)weights);

    spmm2_csr_kernel<<<ROWS_GRID, T>>>(out4, (const float4*)bias_vec);
}

// round 12
// speedup vs baseline: 1.0769x; 1.0769x over previous
#include <cuda_runtime.h>
#include <cuda_fp16.h>

#define N_NODES  100000
#define IN_DIM   256
#define OUT_DIM  128
#define FEAT_NNZ 1000000
#define ADJ_NNZ  1600000

#define TILE      1024
#define NBLK      ((N_NODES + TILE - 1) / TILE)   // 98

#define T         256
#define FBH       ((FEAT_NNZ / 2 + T - 1) / T)    // feat blocks, 2 entries/thread
#define ABH       ((ADJ_NNZ  / 2 + T - 1) / T)    // adj  blocks, 2 entries/thread
#define ROWS_GRID ((N_NODES + 7) / 8)             // 12500 spmm row blocks

// ---------------------------------------------------------------------------
// Scratch (__device__ globals; zero-initialized at module load; referenced
// ONLY from device code). cnt arrays are re-zeroed by scan_p3 after use so
// every graph replay sees identical initial state.
// ---------------------------------------------------------------------------
__device__ uint2  g_xw2[(size_t)N_NODES * 32];            // XW fp16, 25.6 MB

__device__ int    g_feat_cnt [N_NODES];
__device__ int    g_feat_ptr [N_NODES + 1];
__device__ int    g_feat_rank[FEAT_NNZ];                  // within-row rank
__device__ float2 g_feat_csr [FEAT_NNZ];                  // {val, (col*32) bits}
__device__ int    g_feat_bsum[NBLK];

__device__ int    g_adj_cnt [N_NODES];
__device__ int    g_adj_ptr [N_NODES + 1];
__device__ int    g_adj_rank[ADJ_NNZ];
__device__ uint2  g_adj_csr [ADJ_NNZ];                    // {val as half2-dup, col*32}
__device__ int    g_adj_bsum[NBLK];

// ---------------------------------------------------------------------------
// 1. Fused row histogram, 2 entries/thread, capturing each entry's
//    within-row rank (the atomic's return). Scatter then needs NO atomics.
// ---------------------------------------------------------------------------
__global__ void hist_both_kernel(const int2* __restrict__ feat_rows2,
                                 const int2* __restrict__ adj_rows2) {
    if (blockIdx.x < FBH) {
        int i = blockIdx.x * T + threadIdx.x;      // pair index
        int base = i * 2;
        if (base < FEAT_NNZ) {                     // FEAT_NNZ even -> both valid
            int2 r = __ldg(&feat_rows2[i]);
            g_feat_rank[base]     = atomicAdd(&g_feat_cnt[r.x], 1);
            g_feat_rank[base + 1] = atomicAdd(&g_feat_cnt[r.y], 1);
        }
    } else {
        int i = (blockIdx.x - FBH) * T + threadIdx.x;
        int base = i * 2;
        if (base < ADJ_NNZ) {                      // ADJ_NNZ even -> both valid
            int2 r = __ldg(&adj_rows2[i]);
            g_adj_rank[base]     = atomicAdd(&g_adj_cnt[r.x], 1);
            g_adj_rank[base + 1] = atomicAdd(&g_adj_cnt[r.y], 1);
        }
    }
}

// ---------------------------------------------------------------------------
// 2a. Scan phase 1 (fused): per-tile sums of cnt. First NBLK blocks = feat.
// ---------------------------------------------------------------------------
__global__ void scan_p1_kernel() {
    int which = (blockIdx.x >= NBLK);
    int blk   = which ? (blockIdx.x - NBLK) : blockIdx.x;
    const int* __restrict__ cnt = which ? g_adj_cnt  : g_feat_cnt;
    int* __restrict__ bsum      = which ? g_adj_bsum : g_feat_bsum;

    __shared__ int s[TILE];
    int t   = threadIdx.x;
    int idx = blk * TILE + t;
    s[t] = (idx < N_NODES) ? cnt[idx] : 0;
    __syncthreads();
    for (int off = TILE >> 1; off > 0; off >>= 1) {
        if (t < off) s[t] += s[t + off];
        __syncthreads();
    }
    if (t == 0) bsum[blk] = s[0];
}

// ---------------------------------------------------------------------------
// 2b. Scan phase 3 (fused, self-offsetting): tile offset via masked block
//     reduction over bsum, inclusive tile scan, write ptr, zero cnt.
// ---------------------------------------------------------------------------
__global__ void scan_p3_kernel() {
    int which = (blockIdx.x >= NBLK);
    int blk   = which ? (blockIdx.x - NBLK) : blockIdx.x;
    int* __restrict__ cnt        = which ? g_adj_cnt  : g_feat_cnt;
    const int* __restrict__ bsum = which ? g_adj_bsum : g_feat_bsum;
    int* __restrict__ ptr        = which ? g_adj_ptr  : g_feat_ptr;

    __shared__ int s[TILE];
    __shared__ int red[128];
    int t = threadIdx.x;

    if (t < 128) red[t] = (t < NBLK && t < blk) ? bsum[t] : 0;
    __syncthreads();
    for (int off = 64; off > 0; off >>= 1) {
        if (t < off) red[t] += red[t + off];
        __syncthreads();
    }
    int boff = red[0];
    __syncthreads();

    int idx = blk * TILE + t;
    int v   = (idx < N_NODES) ? cnt[idx] : 0;
    s[t] = v;
    __syncthreads();
    for (int off = 1; off < TILE; off <<= 1) {
        int u = (t >= off) ? s[t - off] : 0;
        __syncthreads();
        s[t] += u;
        __syncthreads();
    }

    if (idx < N_NODES) {
        ptr[idx] = boff + s[t] - v;
        cnt[idx] = 0;                               // replay invariant
    }
    if (blk == NBLK - 1 && t == TILE - 1) ptr[N_NODES] = boff + s[t];
}

// ---------------------------------------------------------------------------
// 3. Feat scatter, 2 entries/thread — no atomics. Stores {val, (col*32) bits}
//    so SpMM1 has zero index arithmetic beyond an add.
// ---------------------------------------------------------------------------
__global__ void scatter_feat_kernel(const float2* __restrict__ feat_vals2,
                                    const int2*   __restrict__ feat_rows2,
                                    const int2*   __restrict__ feat_cols2) {
    int i = blockIdx.x * T + threadIdx.x;           // pair index
    int base = i * 2;
    if (base >= FEAT_NNZ) return;                   // FEAT_NNZ even -> both valid
    int2   r = __ldg(&feat_rows2[i]);
    int2   c = __ldg(&feat_cols2[i]);
    float2 v = __ldg(&feat_vals2[i]);
    int2   k = __ldg(&((const int2*)g_feat_rank)[i]);
    int p0 = __ldg(&g_feat_ptr[r.x]) + k.x;
    int p1 = __ldg(&g_feat_ptr[r.y]) + k.y;
    g_feat_csr[p0] = make_float2(v.x, __int_as_float(c.x * 32));
    g_feat_csr[p1] = make_float2(v.y, __int_as_float(c.y * 32));
}

// ---------------------------------------------------------------------------
// 4. FUSED: blocks [0, ABH) scatter the adj COO into CSR (2 entries/thread,
//    value pre-converted to a duplicated half2, column pre-multiplied by 32);
//    blocks [ABH, ...) run SpMM1 over the complete feat CSR. Disjoint data.
// ---------------------------------------------------------------------------
__global__ void adj_scatter_spmm1_kernel(const float2* __restrict__ adj_vals2,
                                         const int2*   __restrict__ adj_rows2,
                                         const int2*   __restrict__ adj_cols2,
                                         const float4* __restrict__ W4) {
    if (blockIdx.x < ABH) {
        // ---- adj scatter, 2 entries/thread ----
        int i = blockIdx.x * T + threadIdx.x;       // pair index
        int base = i * 2;
        if (base >= ADJ_NNZ) return;                // ADJ_NNZ even -> both valid
        int2   r = __ldg(&adj_rows2[i]);
        int2   c = __ldg(&adj_cols2[i]);
        float2 v = __ldg(&adj_vals2[i]);
        int2   k = __ldg(&((const int2*)g_adj_rank)[i]);
        int p0 = __ldg(&g_adj_ptr[r.x]) + k.x;
        int p1 = __ldg(&g_adj_ptr[r.y]) + k.y;
        __half2 h0 = __float2half2_rn(v.x);
        __half2 h1 = __float2half2_rn(v.y);
        g_adj_csr[p0] = make_uint2(*reinterpret_cast<unsigned int*>(&h0),
                                   (unsigned int)(c.x * 32));
        g_adj_csr[p1] = make_uint2(*reinterpret_cast<unsigned int*>(&h1),
                                   (unsigned int)(c.y * 32));
        return;
    }

    // ---- SpMM1: XW[row,:] = sum_e val_e * W[col_e,:] (fp32, fp16 store) ----
    int b    = blockIdx.x - ABH;
    int row  = b * (T >> 5) + (threadIdx.x >> 5);
    if (row >= N_NODES) return;
    int lane = threadIdx.x & 31;

    int s = g_feat_ptr[row];
    int e = g_feat_ptr[row + 1];

    float4 acc = make_float4(0.f, 0.f, 0.f, 0.f);
    int j = s;
    for (; j + 2 <= e; j += 2) {
        float2 vc0 = __ldg(&g_feat_csr[j]);
        float2 vc1 = __ldg(&g_feat_csr[j + 1]);
        float4 w0 = __ldg(&W4[__float_as_int(vc0.y) + lane]);   // coloff pre-*32
        float4 w1 = __ldg(&W4[__float_as_int(vc1.y) + lane]);
        acc.x += vc0.x * w0.x + vc1.x * w1.x;
        acc.y += vc0.x * w0.y + vc1.x * w1.y;
        acc.z += vc0.x * w0.z + vc1.x * w1.z;
        acc.w += vc0.x * w0.w + vc1.x * w1.w;
    }
    for (; j < e; j++) {
        float2 vc = __ldg(&g_feat_csr[j]);
        float4 w = __ldg(&W4[__float_as_int(vc.y) + lane]);
        acc.x += vc.x * w.x;
        acc.y += vc.x * w.y;
        acc.z += vc.x * w.z;
        acc.w += vc.x * w.w;
    }
    __half2 h0 = __floats2half2_rn(acc.x, acc.y);
    __half2 h1 = __floats2half2_rn(acc.z, acc.w);
    uint2 packed;
    packed.x = *reinterpret_cast<unsigned int*>(&h0);
    packed.y = *reinterpret_cast<unsigned int*>(&h1);
    g_xw2[(size_t)row * 32 + lane] = packed;
}

// ---------------------------------------------------------------------------
// 5. SpMM2 — half2 inner loop (2 HFMA2 per edge, zero converts), chunked
//    fp32 flush every 4 edges for accumulation precision. Fused bias+ReLU.
// ---------------------------------------------------------------------------
__global__ void spmm2_csr_kernel(float4* __restrict__ out4,
                                 const float4* __restrict__ bias4) {
    int row  = blockIdx.x * (T >> 5) + (threadIdx.x >> 5);
    if (row >= N_NODES) return;
    int lane = threadIdx.x & 31;

    int s = g_adj_ptr[row];
    int e = g_adj_ptr[row + 1];

    float4 acc = make_float4(0.f, 0.f, 0.f, 0.f);
    int j = s;
    for (; j + 4 <= e; j += 4) {
        uint2 e0 = __ldg(&g_adj_csr[j]);
        uint2 e1 = __ldg(&g_adj_csr[j + 1]);
        uint2 e2 = __ldg(&g_adj_csr[j + 2]);
        uint2 e3 = __ldg(&g_adj_csr[j + 3]);
        uint2 x0 = __ldg(&g_xw2[e0.y + lane]);
        uint2 x1 = __ldg(&g_xw2[e1.y + lane]);
        uint2 x2 = __ldg(&g_xw2[e2.y + lane]);
        uint2 x3 = __ldg(&g_xw2[e3.y + lane]);

        __half2 v0 = *reinterpret_cast<__half2*>(&e0.x);
        __half2 v1 = *reinterpret_cast<__half2*>(&e1.x);
        __half2 v2 = *reinterpret_cast<__half2*>(&e2.x);
        __half2 v3 = *reinterpret_cast<__half2*>(&e3.x);

        // chunk of 4 edges in half2 (cols 0-1 in sA, cols 2-3 in sB)
        __half2 sA = __hmul2(v0, *reinterpret_cast<__half2*>(&x0.x));
        __half2 sB = __hmul2(v0, *reinterpret_cast<__half2*>(&x0.y));
        sA = __hfma2(v1, *reinterpret_cast<__half2*>(&x1.x), sA);
        sB = __hfma2(v1, *reinterpret_cast<__half2*>(&x1.y), sB);
        sA = __hfma2(v2, *reinterpret_cast<__half2*>(&x2.x), sA);
        sB = __hfma2(v2, *reinterpret_cast<__half2*>(&x2.y), sB);
        sA = __hfma2(v3, *reinterpret_cast<__half2*>(&x3.x), sA);
        sB = __hfma2(v3, *reinterpret_cast<__half2*>(&x3.y), sB);

        float2 fA = __half22float2(sA);
        float2 fB = __half22float2(sB);
        acc.x += fA.x;
        acc.y += fA.y;
        acc.z += fB.x;
        acc.w += fB.y;
    }
    for (; j < e; j++) {
        uint2 ej = __ldg(&g_adj_csr[j]);
        uint2 xr = __ldg(&g_xw2[ej.y + lane]);
        __half2 vj = *reinterpret_cast<__half2*>(&ej.x);
        float2 f0 = __half22float2(__hmul2(vj, *reinterpret_cast<__half2*>(&xr.x)));
        float2 f1 = __half22float2(__hmul2(vj, *reinterpret_cast<__half2*>(&xr.y)));
        acc.x += f0.x;
        acc.y += f0.y;
        acc.z += f1.x;
        acc.w += f1.y;
    }

    float4 b = __ldg(&bias4[lane]);
    acc.x = fmaxf(acc.x + b.x, 0.f);
    acc.y = fmaxf(acc.y + b.y, 0.f);
    acc.z = fmaxf(acc.z + b.z, 0.f);
    acc.w = fmaxf(acc.w + b.w, 0.f);
    out4[(size_t)row * 32 + lane] = acc;
}

// ---------------------------------------------------------------------------
extern "C" void kernel_launch(void* const* d_in, const int* in_sizes, int n_in,
                              void* d_out, int out_size) {
    const float* feat_vals = (const float*)d_in[0];
    const int*   feat_rows = (const int*)  d_in[1];
    const int*   feat_cols = (const int*)  d_in[2];
    const float* adj_vals  = (const float*)d_in[3];
    const int*   adj_rows  = (const int*)  d_in[4];
    const int*   adj_cols  = (const int*)  d_in[5];
    const float* weights   = (const float*)d_in[6];
    const float* bias_vec  = (const float*)d_in[7];
    float4* out4 = (float4*)d_out;

    hist_both_kernel<<<FBH + ABH, T>>>((const int2*)feat_rows,
                                       (const int2*)adj_rows);

    scan_p1_kernel<<<2 * NBLK, TILE>>>();
    scan_p3_kernel<<<2 * NBLK, TILE>>>();

    scatter_feat_kernel<<<FBH, T>>>((const float2*)feat_vals,
                                    (const int2*)feat_rows,
                                    (const int2*)feat_cols);

    adj_scatter_spmm1_kernel<<<ABH + ROWS_GRID, T>>>((const float2*)adj_vals,
                                                     (const int2*)adj_rows,
                                                     (const int2*)adj_cols,
                                                     (const float4*)weights);

    spmm2_csr_kernel<<<ROWS_GRID, T>>>(out4, (const float4*)bias_vec);
}